// round 10
// baseline (speedup 1.0000x reference)
#include <cuda_runtime.h>

// LSTM (H=64, in=1, T=1024, B=4096) + Linear(64->30), fp32.
// 147 blocks (1/SM), 256 threads:
//   rp    = tid&1      : row-pair. rp0 -> gate rows {j, 128+j} (i,g);
//                        rp1 -> rows {64+j, 192+j} (f,o). FULL k=64 per thread.
//   j     = (tid>>1)&63: hidden unit
//   bhalf = tid>>7     : which 14 of 28 batches
// Per batch: 64 FFMA2 over the full k (bias+x seeded into the accumulator),
// one lo+hi FADD per row, ONE packed shfl.bfly(1) exchanging the completed
// (i,g)<->(f,o) gate pair. Ownership: rp0 updates batches s=0..6, rp1 s=7..13
// (gate order fixed inside each predicated path -> no selects). h reads are
// warp-uniform broadcast LDS.128. c in registers; h/x ping-pong; 1 barrier/step.

#define HID      64
#define SEQ_T    1024
#define NBATCH   4096
#define NFC      30
#define NB       28
#define NBG      14       // batches per bhalf group
#define NTHREADS 256
#define XCHUNK   32
#define BOWN     7        // batches owned per thread for c/h update

__device__ __forceinline__ float fast_ex2(float x) {
    float r; asm("ex2.approx.f32 %0, %1;" : "=f"(r) : "f"(x)); return r;
}
__device__ __forceinline__ float fast_rcp(float x) {
    float r; asm("rcp.approx.f32 %0, %1;" : "=f"(r) : "f"(x)); return r;
}
__device__ __forceinline__ float sigm(float x) {
    return fast_rcp(1.0f + fast_ex2(-1.4426950408889634f * x));
}
__device__ __forceinline__ float tanh_fast(float x) {
    return 1.0f - 2.0f * fast_rcp(1.0f + fast_ex2(2.8853900817779268f * x));
}

__device__ __forceinline__ unsigned long long pack2(float lo, float hi) {
    unsigned long long r;
    asm("mov.b64 %0, {%1, %2};" : "=l"(r) : "f"(lo), "f"(hi));
    return r;
}
__device__ __forceinline__ void unpack2(unsigned long long v, float& lo, float& hi) {
    asm("mov.b64 {%0, %1}, %2;" : "=f"(lo), "=f"(hi) : "l"(v));
}
__device__ __forceinline__ void ffma2(unsigned long long& d,
                                      unsigned long long a,
                                      unsigned long long b) {
    asm("fma.rn.f32x2 %0, %1, %2, %0;" : "+l"(d) : "l"(a), "l"(b));
}

__global__ void __launch_bounds__(NTHREADS, 1)
lstm_fused(const float* __restrict__ x,      // [B, T]
           const float* __restrict__ W_ih,   // [256]
           const float* __restrict__ W_hh,   // [256, 64]
           const float* __restrict__ b_ih,   // [256]
           const float* __restrict__ b_hh,   // [256]
           const float* __restrict__ fc_W,   // [30, 64]
           const float* __restrict__ fc_b,   // [30]
           float* __restrict__ out)          // [B, 30]
{
    __shared__ __align__(16) float h_sm[2][NB][HID];     // ping-pong hidden
    __shared__ __align__(16) float x_sm[2][NB][XCHUNK];  // ping-pong x chunks
    __shared__ __align__(16) float fcW_sm[NFC][HID];
    __shared__ float fcb_sm[NFC];

    const int tid   = threadIdx.x;
    const int rp    = tid & 1;          // row-pair selector
    const int j     = (tid >> 1) & 63;  // hidden unit
    const int bhalf = tid >> 7;         // batch half (0/1)
    const int b0    = blockIdx.x * NB;
    const int bbase = bhalf * NBG;

    // --- rows owned: rA = rp*64+j (i or f), rB = 128+rp*64+j (g or o) ---
    const int rA = rp * HID + j;
    const int rB = 2 * HID + rp * HID + j;

    // full-k weights: 2 rows x 64 = 128 floats as 64 f32x2 regs
    unsigned long long wA[HID / 2], wB[HID / 2];
#pragma unroll
    for (int k = 0; k < HID / 2; ++k) {
        wA[k] = pack2(W_hh[rA * HID + 2 * k], W_hh[rA * HID + 2 * k + 1]);
        wB[k] = pack2(W_hh[rB * HID + 2 * k], W_hh[rB * HID + 2 * k + 1]);
    }
    const float wihA = W_ih[rA], wihB = W_ih[rB];
    const float bA = b_ih[rA] + b_hh[rA];
    const float bB = b_ih[rB] + b_hh[rB];

    // --- FC weights to smem; h buf0 zero; x buf0 prologue (t=0..31) ---
    for (int i = tid; i < NFC * HID; i += NTHREADS)
        (&fcW_sm[0][0])[i] = fc_W[i];
    for (int i = tid; i < NFC; i += NTHREADS)
        fcb_sm[i] = fc_b[i];
    for (int i = tid; i < NB * HID; i += NTHREADS)
        (&h_sm[0][0][0])[i] = 0.0f;
    for (int i = tid; i < NB * XCHUNK; i += NTHREADS) {
        int b  = i / XCHUNK;
        int tt = i % XCHUNK;
        int gb = b0 + b; if (gb >= NBATCH) gb = NBATCH - 1;
        (&x_sm[0][0][0])[i] = x[gb * SEQ_T + tt];
    }

    float c_reg[BOWN];
#pragma unroll
    for (int s = 0; s < BOWN; ++s) c_reg[s] = 0.0f;

    __syncthreads();

    for (int t = 0; t < SEQ_T; ++t) {
        const int rb = t & 1;           // h read buffer
        const int wb = rb ^ 1;          // h write buffer
        const int xb = (t >> 5) & 1;    // x read buffer

        // prefetch NEXT x chunk into the other buffer
        if ((t & (XCHUNK - 1)) == 0 && t + XCHUNK < SEQ_T) {
            for (int i = tid; i < NB * XCHUNK; i += NTHREADS) {
                int b  = i / XCHUNK;
                int tt = i % XCHUNK;
                int gb = b0 + b; if (gb >= NBATCH) gb = NBATCH - 1;
                x_sm[xb ^ 1][b][tt] = x[gb * SEQ_T + t + XCHUNK + tt];
            }
        }
        __syncthreads();  // h[rb] from prev step + x visible

        const int tx = t & (XCHUNK - 1);
        float gq[BOWN][4];  // gates (i,f,g,o) of the 7 batches this thread owns

#pragma unroll
        for (int s = 0; s < NBG; ++s) {
            const int b = bbase + s;
            const char* hbase = (const char*)&h_sm[rb][b][0];

            // seed accumulators with bias + x term (lane0 of the pair)
            const float xv = x_sm[xb][b][tx];
            unsigned long long aA = pack2(fmaf(xv, wihA, bA), 0.0f);
            unsigned long long aB = pack2(fmaf(xv, wihB, bB), 0.0f);

#pragma unroll
            for (int c = 0; c < 16; ++c) {
                ulonglong2 hv = *(const ulonglong2*)(hbase + c * 16);  // bcast
                ffma2(aA, wA[2 * c],     hv.x);
                ffma2(aA, wA[2 * c + 1], hv.y);
                ffma2(aB, wB[2 * c],     hv.x);
                ffma2(aB, wB[2 * c + 1], hv.y);
            }
            float lo, hi, gA, gB;
            unpack2(aA, lo, hi); gA = lo + hi;   // complete gate (i or f)
            unpack2(aB, lo, hi); gB = lo + hi;   // complete gate (g or o)

            // ONE packed exchange with the paired lane: (i,g) <-> (f,o)
            unsigned long long p = pack2(gA, gB);
            unsigned long long o = __shfl_xor_sync(0xffffffffu, p, 1);
            float oA, oB;
            unpack2(o, oA, oB);

            // ownership: rp0 -> s=0..6 (own=(i,g), other=(f,o));
            //            rp1 -> s=7..13 (own=(f,o), other=(i,g))
            if (s < BOWN) {
                if (rp == 0) {
                    gq[s][0] = gA;  gq[s][1] = oA;   // i, f
                    gq[s][2] = gB;  gq[s][3] = oB;   // g, o
                }
            } else {
                if (rp == 1) {
                    gq[s - BOWN][0] = oA;  gq[s - BOWN][1] = gA;  // i, f
                    gq[s - BOWN][2] = oB;  gq[s - BOWN][3] = gB;  // g, o
                }
            }
        }

        // ---- update phase: each thread updates its 7 owned batches ----
#pragma unroll
        for (int q = 0; q < BOWN; ++q) {
            const int b = bbase + rp * BOWN + q;
            float ci = fmaf(sigm(gq[q][1]), c_reg[q],
                            sigm(gq[q][0]) * tanh_fast(gq[q][2]));
            c_reg[q] = ci;
            h_sm[wb][b][j] = sigm(gq[q][3]) * tanh_fast(ci);
        }
    }

    __syncthreads();  // final h (buffer 0, SEQ_T even) ready

    // ---- FC: out[b, f] = h[b,:] . fc_W[f,:] + fc_b[f] ----
    for (int task = tid; task < NB * NFC; task += NTHREADS) {
        int b = task / NFC;
        int f = task % NFC;
        int gb = b0 + b;
        if (gb < NBATCH) {
            float s = fcb_sm[f];
#pragma unroll
            for (int k = 0; k < HID; ++k)
                s = fmaf(h_sm[0][b][k], fcW_sm[f][k], s);
            out[gb * NFC + f] = s;
        }
    }
}

extern "C" void kernel_launch(void* const* d_in, const int* in_sizes, int n_in,
                              void* d_out, int out_size) {
    const float* x    = (const float*)d_in[0];
    const float* W_ih = (const float*)d_in[1];
    const float* W_hh = (const float*)d_in[2];
    const float* b_ih = (const float*)d_in[3];
    const float* b_hh = (const float*)d_in[4];
    const float* fc_W = (const float*)d_in[5];
    const float* fc_b = (const float*)d_in[6];
    (void)in_sizes; (void)n_in; (void)out_size;

    const int grid = (NBATCH + NB - 1) / NB;  // 147 blocks, 1 per SM
    lstm_fused<<<grid, NTHREADS>>>(x, W_ih, W_hh, b_ih, b_hh, fc_W, fc_b,
                                   (float*)d_out);
}